// round 4
// baseline (speedup 1.0000x reference)
#include <cuda_runtime.h>
#include <math.h>

// Problem constants
#define S_LEN   2048
#define NH      16
#define HD      64
#define BH_TOT  32          // B * NH
#define M_ROWS  4096        // B * S
#define H_DIM   1024
#define QKV_N   3072

// -------- scratch (device globals: no allocation allowed) --------
__device__ float g_qkv[(size_t)M_ROWS * QKV_N];          // 50.3 MB
__device__ float g_q[(size_t)BH_TOT * S_LEN * HD];       // 16.8 MB
__device__ float g_k[(size_t)BH_TOT * S_LEN * HD];
__device__ float g_v[(size_t)BH_TOT * S_LEN * HD];
__device__ float g_attn[(size_t)M_ROWS * H_DIM];         // 16.8 MB
__device__ float g_cos[S_LEN * 32];
__device__ float g_sin[S_LEN * 32];

// =================================================================
// RoPE tables: inv_freq[j] = 10000^(-j/32), j in [0,32)
// Computed in double so the float32 table matches jnp to ~1 ulp.
// =================================================================
__global__ void init_rope_tables() {
    int idx = blockIdx.x * blockDim.x + threadIdx.x;
    if (idx >= S_LEN * 32) return;
    int s = idx >> 5;
    int j = idx & 31;
    double invf = exp(-log(10000.0) * (double)j / 32.0);
    double ang  = (double)s * invf;
    g_cos[idx] = (float)cos(ang);
    g_sin[idx] = (float)sin(ang);
}

// =================================================================
// SGEMM: C[M][N] = A[M][K] * B[N][K]^T   (both operands K-major)
// 128x128 CTA tile, BK=8, 256 threads, 8x8 per-thread tile,
// double-buffered shared memory with register prefetch.
// Requires M%128==0, N%128==0, K%8==0 (all shapes here comply).
// =================================================================
__device__ __forceinline__ void sgemm_body(
    const float* __restrict__ A, const float* __restrict__ B,
    float* __restrict__ C, int M, int N, int K)
{
    __shared__ __align__(16) float As[2][8][128];
    __shared__ __align__(16) float Bs[2][8][128];

    const int tid = threadIdx.x;
    const int bm = blockIdx.y * 128;
    const int bn = blockIdx.x * 128;

    const int lr = tid >> 1;            // 0..127: row within tile
    const int lk = (tid & 1) << 2;      // 0 or 4: k offset

    const float* Ald = A + (size_t)(bm + lr) * K + lk;
    const float* Bld = B + (size_t)(bn + lr) * K + lk;

    float4 a4 = *(const float4*)Ald;
    float4 b4 = *(const float4*)Bld;
    As[0][lk + 0][lr] = a4.x; As[0][lk + 1][lr] = a4.y;
    As[0][lk + 2][lr] = a4.z; As[0][lk + 3][lr] = a4.w;
    Bs[0][lk + 0][lr] = b4.x; Bs[0][lk + 1][lr] = b4.y;
    Bs[0][lk + 2][lr] = b4.z; Bs[0][lk + 3][lr] = b4.w;
    __syncthreads();

    float acc[8][8] = {};
    const int rm = (tid >> 4) << 3;     // row block 0..120
    const int cn = (tid & 15) << 3;     // col block 0..120

    const int nIter = K >> 3;
    for (int it = 0; it < nIter; ++it) {
        const int cur = it & 1;
        const bool pf = (it + 1) < nIter;
        if (pf) {
            a4 = *(const float4*)(Ald + (size_t)(it + 1) * 8);
            b4 = *(const float4*)(Bld + (size_t)(it + 1) * 8);
        }
#pragma unroll
        for (int k = 0; k < 8; ++k) {
            float4 a0 = *(const float4*)&As[cur][k][rm];
            float4 a1 = *(const float4*)&As[cur][k][rm + 4];
            float4 b0 = *(const float4*)&Bs[cur][k][cn];
            float4 b1 = *(const float4*)&Bs[cur][k][cn + 4];
            float av[8] = {a0.x, a0.y, a0.z, a0.w, a1.x, a1.y, a1.z, a1.w};
            float bv[8] = {b0.x, b0.y, b0.z, b0.w, b1.x, b1.y, b1.z, b1.w};
#pragma unroll
            for (int i = 0; i < 8; ++i)
#pragma unroll
                for (int j = 0; j < 8; ++j)
                    acc[i][j] += av[i] * bv[j];
        }
        if (pf) {
            const int nxt = cur ^ 1;
            As[nxt][lk + 0][lr] = a4.x; As[nxt][lk + 1][lr] = a4.y;
            As[nxt][lk + 2][lr] = a4.z; As[nxt][lk + 3][lr] = a4.w;
            Bs[nxt][lk + 0][lr] = b4.x; Bs[nxt][lk + 1][lr] = b4.y;
            Bs[nxt][lk + 2][lr] = b4.z; Bs[nxt][lk + 3][lr] = b4.w;
        }
        __syncthreads();
    }

#pragma unroll
    for (int i = 0; i < 8; ++i) {
        float* Cp = C + (size_t)(bm + rm + i) * N + bn + cn;
        *(float4*)(Cp)     = make_float4(acc[i][0], acc[i][1], acc[i][2], acc[i][3]);
        *(float4*)(Cp + 4) = make_float4(acc[i][4], acc[i][5], acc[i][6], acc[i][7]);
    }
}

__global__ void __launch_bounds__(256) k_gemm_qkv(
    const float* __restrict__ x, const float* __restrict__ W)
{
    sgemm_body(x, W, g_qkv, M_ROWS, QKV_N, H_DIM);
}

__global__ void __launch_bounds__(256) k_gemm_proj(
    const float* __restrict__ W, float* __restrict__ out)
{
    sgemm_body(g_attn, W, out, M_ROWS, H_DIM, H_DIM);
}

// =================================================================
// RoPE + permute: g_qkv[4096][3072] -> g_q/g_k/g_v [bh][s][d]
// RoPE on q,k dims [0,32): out[d] = x[d]*cos[s,d] + rot*sin[s,d]
//   rot = -x[d+16] (d<16)  |  x[d-16] (d>=16).  Dims [32,64) copied.
// =================================================================
__global__ void __launch_bounds__(256) rope_permute() {
    int idx = blockIdx.x * blockDim.x + threadIdx.x;    // < 3 * 2^22
    if (idx >= (3 << 22)) return;
    const int d      = idx & 63;
    const int s      = (idx >> 6) & 2047;
    const int bh     = (idx >> 17) & 31;
    const int region = idx >> 22;                       // 0=q 1=k 2=v
    const int b = bh >> 4, h = bh & 15;
    const int m = b * S_LEN + s;

    const float* src = g_qkv + (size_t)m * QKV_N + region * H_DIM + h * HD;
    float val;
    if (region == 2 || d >= 32) {
        val = src[d];
    } else {
        const float c  = g_cos[s * 32 + d];
        const float sn = g_sin[s * 32 + d];
        const float x0 = src[d];
        const float xr = (d < 16) ? -src[d + 16] : src[d - 16];
        val = x0 * c + xr * sn;
    }
    float* dst = (region == 0) ? g_q : (region == 1) ? g_k : g_v;
    dst[((size_t)bh * S_LEN + s) * HD + d] = val;
}

// =================================================================
// Flash attention (non-causal, full softmax over S=2048).
// CTA: (64-row Q tile, bh). 256 threads = 16x16; 4x4 per thread.
// Phase 1: S = Q K^T * scale (Q,K stored dim-major in smem).
// Online softmax: 16-lane shuffle reductions across tx.
// Phase 2: P (transposed in smem) @ V.
// Dynamic smem: 4 * 64 * 68 * 4 B = 69632 B.
// =================================================================
__global__ void __launch_bounds__(256) flash_attn() {
    extern __shared__ __align__(16) float smem[];
    float (*Qt)[68] = (float (*)[68])(smem);                 // [d][r]
    float (*Kt)[68] = (float (*)[68])(smem + 1 * 64 * 68);   // [d][c]
    float (*Vs)[68] = (float (*)[68])(smem + 2 * 64 * 68);   // [c][d]
    float (*Pt)[68] = (float (*)[68])(smem + 3 * 64 * 68);   // [c][r]

    const int tid = threadIdx.x;
    const int ty = tid >> 4, tx = tid & 15;
    const int r0 = ty * 4;          // rows owned (both phases)
    const int c0 = tx * 4;          // score cols owned (phase 1)
    const int d0 = tx * 4;          // out dims owned (phase 2)

    const int q0 = blockIdx.x * 64;
    const int bh = blockIdx.y;

    const float* Qg = g_q + ((size_t)bh * S_LEN + q0) * HD;
    const float* Kb = g_k + (size_t)bh * S_LEN * HD;
    const float* Vb = g_v + (size_t)bh * S_LEN * HD;

    for (int i = tid; i < 64 * 64; i += 256) {
        int r = i >> 6, d = i & 63;
        Qt[d][r] = Qg[i];
    }

    float mrun[4], lrun[4], acc[4][4];
#pragma unroll
    for (int i = 0; i < 4; ++i) {
        mrun[i] = -1e30f; lrun[i] = 0.f;
#pragma unroll
        for (int j = 0; j < 4; ++j) acc[i][j] = 0.f;
    }

    for (int jt = 0; jt < S_LEN / 64; ++jt) {
        __syncthreads();   // prev phase-2 reads done before Kt/Vs/Pt overwrite
        const float* Kg = Kb + (size_t)jt * 64 * HD;
        const float* Vg = Vb + (size_t)jt * 64 * HD;
        for (int i = tid; i < 64 * 64; i += 256) {
            int c = i >> 6, d = i & 63;
            Kt[d][c] = Kg[i];
            Vs[c][d] = Vg[i];
        }
        __syncthreads();

        // ---- phase 1: scores ----
        float s[4][4] = {};
#pragma unroll 8
        for (int k = 0; k < 64; ++k) {
            float4 q4 = *(const float4*)&Qt[k][r0];
            float4 k4 = *(const float4*)&Kt[k][c0];
            float qa[4] = {q4.x, q4.y, q4.z, q4.w};
            float kb[4] = {k4.x, k4.y, k4.z, k4.w};
#pragma unroll
            for (int i = 0; i < 4; ++i)
#pragma unroll
                for (int j = 0; j < 4; ++j)
                    s[i][j] += qa[i] * kb[j];
        }
#pragma unroll
        for (int i = 0; i < 4; ++i)
#pragma unroll
            for (int j = 0; j < 4; ++j)
                s[i][j] *= 0.125f;   // 1/sqrt(64)

        // row max across the 16 tx lanes
        float rmax[4];
#pragma unroll
        for (int i = 0; i < 4; ++i)
            rmax[i] = fmaxf(fmaxf(s[i][0], s[i][1]), fmaxf(s[i][2], s[i][3]));
#pragma unroll
        for (int off = 1; off < 16; off <<= 1)
#pragma unroll
            for (int i = 0; i < 4; ++i)
                rmax[i] = fmaxf(rmax[i], __shfl_xor_sync(0xffffffffu, rmax[i], off));

        float alpha[4];
#pragma unroll
        for (int i = 0; i < 4; ++i) {
            float mn = fmaxf(mrun[i], rmax[i]);
            alpha[i] = __expf(mrun[i] - mn);
            mrun[i] = mn;
        }
#pragma unroll
        for (int i = 0; i < 4; ++i)
#pragma unroll
            for (int j = 0; j < 4; ++j)
                s[i][j] = __expf(s[i][j] - mrun[i]);

        float rsum[4];
#pragma unroll
        for (int i = 0; i < 4; ++i)
            rsum[i] = (s[i][0] + s[i][1]) + (s[i][2] + s[i][3]);
#pragma unroll
        for (int off = 1; off < 16; off <<= 1)
#pragma unroll
            for (int i = 0; i < 4; ++i)
                rsum[i] += __shfl_xor_sync(0xffffffffu, rsum[i], off);

#pragma unroll
        for (int i = 0; i < 4; ++i) {
            lrun[i] = lrun[i] * alpha[i] + rsum[i];
#pragma unroll
            for (int j = 0; j < 4; ++j) acc[i][j] *= alpha[i];
        }

        // stage P transposed: Pt[c][r]
#pragma unroll
        for (int cc = 0; cc < 4; ++cc)
            *(float4*)&Pt[c0 + cc][r0] =
                make_float4(s[0][cc], s[1][cc], s[2][cc], s[3][cc]);
        __syncthreads();

        // ---- phase 2: acc += P^T-tile @ V ----
#pragma unroll 8
        for (int c = 0; c < 64; ++c) {
            float4 p4 = *(const float4*)&Pt[c][r0];
            float4 v4 = *(const float4*)&Vs[c][d0];
            float pa[4] = {p4.x, p4.y, p4.z, p4.w};
            float vb[4] = {v4.x, v4.y, v4.z, v4.w};
#pragma unroll
            for (int i = 0; i < 4; ++i)
#pragma unroll
                for (int j = 0; j < 4; ++j)
                    acc[i][j] += pa[i] * vb[j];
        }
    }

    // epilogue: normalize, write [m][h*64+d] layout for proj GEMM
    const int b = bh >> 4, h = bh & 15;
    float* Og = g_attn + ((size_t)(b * S_LEN + q0 + r0)) * H_DIM + h * HD + d0;
#pragma unroll
    for (int i = 0; i < 4; ++i) {
        float inv = 1.0f / lrun[i];
        *(float4*)(Og + (size_t)i * H_DIM) =
            make_float4(acc[i][0] * inv, acc[i][1] * inv,
                        acc[i][2] * inv, acc[i][3] * inv);
    }
}

// =================================================================
// launch
// =================================================================
extern "C" void kernel_launch(void* const* d_in, const int* in_sizes, int n_in,
                              void* d_out, int out_size)
{
    const float* x     = (const float*)d_in[0];   // [2,2048,1024]
    const float* Wqkv  = (const float*)d_in[1];   // [3072,1024]
    const float* Wproj = (const float*)d_in[2];   // [1024,1024]
    float* out = (float*)d_out;                   // [2,2048,1024]

    static const size_t FLASH_SMEM = 4 * 64 * 68 * sizeof(float);  // 69632
    cudaFuncSetAttribute(flash_attn,
                         cudaFuncAttributeMaxDynamicSharedMemorySize,
                         (int)FLASH_SMEM);

    init_rope_tables<<<(S_LEN * 32 + 255) / 256, 256>>>();
    k_gemm_qkv<<<dim3(QKV_N / 128, M_ROWS / 128), 256>>>(x, Wqkv);
    rope_permute<<<(3 << 22) / 256, 256>>>();
    flash_attn<<<dim3(S_LEN / 64, BH_TOT), 256, FLASH_SMEM>>>();
    k_gemm_proj<<<dim3(H_DIM / 128, M_ROWS / 128), 256>>>(Wproj, out);
}

// round 5
// speedup vs baseline: 2.1662x; 2.1662x over previous
#include <cuda_runtime.h>
#include <math.h>
#include <stdint.h>

// Problem constants
#define S_LEN   2048
#define NH      16
#define HD      64
#define BH_TOT  32          // B * NH
#define M_ROWS  4096        // B * S
#define H_DIM   1024
#define QKV_N   3072

// -------- scratch (device globals: no allocation allowed) --------
__device__ float g_qkv[(size_t)M_ROWS * QKV_N];          // fp32 QKV GEMM out
__device__ float g_q[(size_t)BH_TOT * S_LEN * HD];       // tf32-rounded
__device__ float g_k[(size_t)BH_TOT * S_LEN * HD];       // tf32-rounded
__device__ float g_v[(size_t)BH_TOT * S_LEN * HD];       // tf32-rounded
__device__ float g_attn[(size_t)M_ROWS * H_DIM];         // tf32-rounded O
__device__ float g_xa[(size_t)M_ROWS * H_DIM];           // tf32-rounded x
__device__ float g_wqkv[(size_t)QKV_N * H_DIM];          // tf32-rounded W_qkv
__device__ float g_wproj[(size_t)H_DIM * H_DIM];         // tf32-rounded W_proj
__device__ float g_cos[S_LEN * 32];
__device__ float g_sin[S_LEN * 32];

// ================= small helpers =================
__device__ __forceinline__ uint32_t f2tf32(float x) {
    uint32_t r; asm("cvt.rna.tf32.f32 %0, %1;" : "=r"(r) : "f"(x)); return r;
}
__device__ __forceinline__ float f2tf32f(float x) { return __uint_as_float(f2tf32(x)); }

__device__ __forceinline__ void mma8(float d[4], const uint32_t a[4], const uint32_t b[2]) {
    asm volatile("mma.sync.aligned.m16n8k8.row.col.f32.tf32.tf32.f32 "
                 "{%0,%1,%2,%3}, {%4,%5,%6,%7}, {%8,%9}, {%0,%1,%2,%3};\n"
                 : "+f"(d[0]), "+f"(d[1]), "+f"(d[2]), "+f"(d[3])
                 : "r"(a[0]), "r"(a[1]), "r"(a[2]), "r"(a[3]),
                   "r"(b[0]), "r"(b[1]));
}

__device__ __forceinline__ void cp16(uint32_t s, const void* g) {
    asm volatile("cp.async.cg.shared.global [%0], [%1], 16;" :: "r"(s), "l"(g));
}
__device__ __forceinline__ void cp_commit() { asm volatile("cp.async.commit_group;"); }
template<int N> __device__ __forceinline__ void cp_wait() {
    asm volatile("cp.async.wait_group %0;" :: "n"(N));
}

// pure-FMA exp2 (degree-6 Taylor on |f|<=0.5; rel err ~1e-7). No MUFU.
__device__ __forceinline__ float fexp2(float x) {
    x = fmaxf(x, -100.f);
    float i = rintf(x);
    float f = x - i;
    float p = fmaf(f, 1.54035304e-4f, 1.33335581e-3f);
    p = fmaf(p, f, 9.61812911e-3f);
    p = fmaf(p, f, 5.55041087e-2f);
    p = fmaf(p, f, 2.40226507e-1f);
    p = fmaf(p, f, 6.93147181e-1f);
    p = fmaf(p, f, 1.0f);
    return __int_as_float(__float_as_int(p) + (((int)i) << 23));
}

// C-fragment (m16n8 f32) -> A-fragment (m16k8 tf32) of the SAME 16x8 tile.
__device__ __forceinline__ void cfrag_to_afrag(const float c[4], uint32_t a[4]) {
    int t = threadIdx.x & 31;
    int src0 = (t & 28) | ((t & 3) >> 1);
    int src2 = src0 + 2;
    float x00 = __shfl_sync(0xffffffffu, c[0], src0);
    float x01 = __shfl_sync(0xffffffffu, c[1], src0);
    float x10 = __shfl_sync(0xffffffffu, c[2], src0);
    float x11 = __shfl_sync(0xffffffffu, c[3], src0);
    float y00 = __shfl_sync(0xffffffffu, c[0], src2);
    float y01 = __shfl_sync(0xffffffffu, c[1], src2);
    float y10 = __shfl_sync(0xffffffffu, c[2], src2);
    float y11 = __shfl_sync(0xffffffffu, c[3], src2);
    bool odd = t & 1;
    a[0] = f2tf32(odd ? x01 : x00);
    a[1] = f2tf32(odd ? x11 : x10);
    a[2] = f2tf32(odd ? y01 : y00);
    a[3] = f2tf32(odd ? y11 : y10);
}

// ================= RoPE tables =================
__global__ void init_rope_tables() {
    int idx = blockIdx.x * blockDim.x + threadIdx.x;
    if (idx >= S_LEN * 32) return;
    int s = idx >> 5;
    int j = idx & 31;
    double invf = exp(-log(10000.0) * (double)j / 32.0);
    double ang  = (double)s * invf;
    g_cos[idx] = (float)cos(ang);
    g_sin[idx] = (float)sin(ang);
}

// ================= tf32 pre-rounding of inputs =================
__global__ void cvt_x(const float* __restrict__ in) {
    int i = (blockIdx.x * blockDim.x + threadIdx.x) * 4;
    if (i >= M_ROWS * H_DIM) return;
    float4 v = *(const float4*)(in + i);
    v.x = f2tf32f(v.x); v.y = f2tf32f(v.y); v.z = f2tf32f(v.z); v.w = f2tf32f(v.w);
    *(float4*)(g_xa + i) = v;
}
__global__ void cvt_wqkv(const float* __restrict__ in) {
    int i = (blockIdx.x * blockDim.x + threadIdx.x) * 4;
    if (i >= QKV_N * H_DIM) return;
    float4 v = *(const float4*)(in + i);
    v.x = f2tf32f(v.x); v.y = f2tf32f(v.y); v.z = f2tf32f(v.z); v.w = f2tf32f(v.w);
    *(float4*)(g_wqkv + i) = v;
}
__global__ void cvt_wproj(const float* __restrict__ in) {
    int i = (blockIdx.x * blockDim.x + threadIdx.x) * 4;
    if (i >= H_DIM * H_DIM) return;
    float4 v = *(const float4*)(in + i);
    v.x = f2tf32f(v.x); v.y = f2tf32f(v.y); v.z = f2tf32f(v.z); v.w = f2tf32f(v.w);
    *(float4*)(g_wproj + i) = v;
}

// ================= tf32 GEMM: C[M][N] = A[M][K] * B[N][K]^T =================
// Inputs A,B hold tf32-rounded bit patterns. CTA 128x128, k-chunk 32,
// 8 warps (4x2), warp tile 32x64, 2-stage cp.async pipeline.
// smem: As[2][128][36] + Bs[2][128][36] = 73728 B (stride 36 == 4 mod 32
// makes every fragment LDS hit 32 distinct banks).
__device__ __forceinline__ void gemm_body(
    const float* __restrict__ A, const float* __restrict__ B,
    float* __restrict__ C, int M, int N, int K)
{
    extern __shared__ float sm[];
    float* As = sm;            // 2 * 128*36 floats
    float* Bs = sm + 2 * 128 * 36;

    const int tid = threadIdx.x;
    const int bm = blockIdx.y * 128, bn = blockIdx.x * 128;

    const int lr = tid >> 1;           // 0..127 row in tile
    const int k0 = (tid & 1) << 4;     // 0 or 16
    const float* Ag = A + (size_t)(bm + lr) * K + k0;
    const float* Bg = B + (size_t)(bn + lr) * K + k0;
    uint32_t sA = (uint32_t)__cvta_generic_to_shared(As) + (lr * 36 + k0) * 4;
    uint32_t sB = (uint32_t)__cvta_generic_to_shared(Bs) + (lr * 36 + k0) * 4;
    const uint32_t bufB = 128 * 36 * 4;

    auto issue = [&](int chunk) {
        int buf = chunk & 1;
        const float* a = Ag + chunk * 32;
        const float* b = Bg + chunk * 32;
        uint32_t da = sA + buf * bufB;
        uint32_t db = sB + buf * bufB;
#pragma unroll
        for (int j = 0; j < 4; ++j) { cp16(da + j * 16, a + j * 4); cp16(db + j * 16, b + j * 4); }
        cp_commit();
    };

    issue(0);

    const int warp = tid >> 5, lane = tid & 31;
    const int g = lane >> 2, q4 = lane & 3;
    const int wm = (warp >> 1) * 32;
    const int wn = (warp & 1) * 64;

    float acc[2][8][4] = {};
    const int nChunks = K >> 5;
    for (int it = 0; it < nChunks; ++it) {
        if (it + 1 < nChunks) { issue(it + 1); cp_wait<1>(); }
        else                  { cp_wait<0>(); }
        __syncthreads();
        const float* Ab = As + (it & 1) * (128 * 36);
        const float* Bb = Bs + (it & 1) * (128 * 36);
#pragma unroll
        for (int kk = 0; kk < 4; ++kk) {
            uint32_t af[2][4];
#pragma unroll
            for (int mi = 0; mi < 2; ++mi) {
                const float* base = Ab + (wm + mi * 16 + g) * 36 + kk * 8 + q4;
                af[mi][0] = __float_as_uint(base[0]);
                af[mi][1] = __float_as_uint(base[8 * 36]);
                af[mi][2] = __float_as_uint(base[4]);
                af[mi][3] = __float_as_uint(base[8 * 36 + 4]);
            }
#pragma unroll
            for (int j = 0; j < 8; ++j) {
                uint32_t bf[2];
                const float* base = Bb + (wn + j * 8 + g) * 36 + kk * 8 + q4;
                bf[0] = __float_as_uint(base[0]);
                bf[1] = __float_as_uint(base[4]);
                mma8(acc[0][j], af[0], bf);
                mma8(acc[1][j], af[1], bf);
            }
        }
        __syncthreads();
    }

#pragma unroll
    for (int mi = 0; mi < 2; ++mi)
#pragma unroll
        for (int r = 0; r < 2; ++r) {
            int row = bm + wm + mi * 16 + g + r * 8;
            float* Cp = C + (size_t)row * N + bn + wn;
#pragma unroll
            for (int j = 0; j < 8; ++j) {
                float2 v = make_float2(acc[mi][j][r * 2], acc[mi][j][r * 2 + 1]);
                *(float2*)(Cp + j * 8 + q4 * 2) = v;
            }
        }
}

__global__ void __launch_bounds__(256) gemm_qkv(const float* __restrict__ unused) {
    gemm_body(g_xa, g_wqkv, g_qkv, M_ROWS, QKV_N, H_DIM);
}
__global__ void __launch_bounds__(256) gemm_proj(float* __restrict__ out) {
    gemm_body(g_attn, g_wproj, out, M_ROWS, H_DIM, H_DIM);
}

// ================= RoPE + permute (writes tf32-rounded) =================
__global__ void __launch_bounds__(256) rope_permute() {
    int idx = blockIdx.x * blockDim.x + threadIdx.x;
    if (idx >= (3 << 22)) return;
    const int d      = idx & 63;
    const int s      = (idx >> 6) & 2047;
    const int bh     = (idx >> 17) & 31;
    const int region = idx >> 22;                       // 0=q 1=k 2=v
    const int b = bh >> 4, h = bh & 15;
    const int m = b * S_LEN + s;

    const float* src = g_qkv + (size_t)m * QKV_N + region * H_DIM + h * HD;
    float val;
    if (region == 2 || d >= 32) {
        val = src[d];
    } else {
        const float c  = g_cos[s * 32 + d];
        const float sn = g_sin[s * 32 + d];
        const float x0 = src[d];
        const float xr = (d < 16) ? -src[d + 16] : src[d - 16];
        val = x0 * c + xr * sn;
    }
    float* dst = (region == 0) ? g_q : (region == 1) ? g_k : g_v;
    dst[((size_t)bh * S_LEN + s) * HD + d] = f2tf32f(val);
}

// ================= Flash attention, tf32 mma + FMA-only softmax =========
// CTA: 128 Q rows x bh. 8 warps; warp owns 16 Q rows (one m16 tile).
// KV chunks of 64, 2-stage cp.async.  smem strides: Q/K 68 (==4 mod 32),
// V 72 (==8 mod 32) -> conflict-free fragment loads.
// smem = (128*68 + 2*64*68 + 2*64*72) * 4 = 106496 B.
__global__ void __launch_bounds__(256) flash_attn() {
    extern __shared__ float sm[];
    float* Qs = sm;                       // 128*68
    float* Ks = sm + 8704;                // 2*64*68
    float* Vs = sm + 8704 + 8704;         // 2*64*72

    const int tid = threadIdx.x;
    const int warp = tid >> 5, lane = tid & 31;
    const int g = lane >> 2, q4 = lane & 3;
    const int q0 = blockIdx.x * 128;
    const int bh = blockIdx.y;

    const float* Qg = g_q + ((size_t)bh * S_LEN + q0) * HD;
    const float* Kb = g_k + (size_t)bh * S_LEN * HD;
    const float* Vb = g_v + (size_t)bh * S_LEN * HD;

    // Q load (part of cp.async group 0)
    {
        int qr = tid >> 1, d0 = (tid & 1) * 32;
        uint32_t dst = (uint32_t)__cvta_generic_to_shared(Qs) + (qr * 68 + d0) * 4;
        const float* src = Qg + qr * 64 + d0;
#pragma unroll
        for (int j = 0; j < 8; ++j) cp16(dst + j * 16, src + j * 4);
    }
    const int kc = tid >> 2, kd = (tid & 3) * 16;
    uint32_t sK = (uint32_t)__cvta_generic_to_shared(Ks) + (kc * 68 + kd) * 4;
    uint32_t sV = (uint32_t)__cvta_generic_to_shared(Vs) + (kc * 72 + kd) * 4;
    auto issueKV = [&](int chunk) {
        int buf = chunk & 1;
        const float* kg = Kb + (size_t)chunk * 64 * 64 + kc * 64 + kd;
        const float* vg = Vb + (size_t)chunk * 64 * 64 + kc * 64 + kd;
        uint32_t dk = sK + buf * (64 * 68 * 4);
        uint32_t dv = sV + buf * (64 * 72 * 4);
#pragma unroll
        for (int j = 0; j < 4; ++j) { cp16(dk + j * 16, kg + j * 4); cp16(dv + j * 16, vg + j * 4); }
        cp_commit();
    };
    issueKV(0);   // group 0 = Q + K0 + V0

    const int wq = warp * 16;
    uint32_t qf[8][4];
    float o[8][4] = {};
    float m0 = -1e30f, m1 = -1e30f, l0 = 0.f, l1 = 0.f;
    const float CE = 0.125f * 1.44269504088896f;   // scale * log2(e)

    const int nChunks = S_LEN / 64;
    for (int it = 0; it < nChunks; ++it) {
        if (it + 1 < nChunks) { issueKV(it + 1); cp_wait<1>(); }
        else                  { cp_wait<0>(); }
        __syncthreads();
        if (it == 0) {
#pragma unroll
            for (int kk = 0; kk < 8; ++kk) {
                const float* base = Qs + (wq + g) * 68 + kk * 8 + q4;
                qf[kk][0] = __float_as_uint(base[0]);
                qf[kk][1] = __float_as_uint(base[8 * 68]);
                qf[kk][2] = __float_as_uint(base[4]);
                qf[kk][3] = __float_as_uint(base[8 * 68 + 4]);
            }
        }
        const float* Kc = Ks + (it & 1) * (64 * 68);
        const float* Vc = Vs + (it & 1) * (64 * 72);

        // ---- scores: S(16x64) = Q Kt ----
        float s[8][4] = {};
#pragma unroll
        for (int kk = 0; kk < 8; ++kk) {
#pragma unroll
            for (int nt = 0; nt < 8; ++nt) {
                uint32_t bf[2];
                const float* base = Kc + (nt * 8 + g) * 68 + kk * 8 + q4;
                bf[0] = __float_as_uint(base[0]);
                bf[1] = __float_as_uint(base[4]);
                mma8(s[nt], qf[kk], bf);
            }
        }

        // ---- online softmax (raw scores; 1/8 scale folded into CE) ----
        float mx0 = -1e30f, mx1 = -1e30f;
#pragma unroll
        for (int nt = 0; nt < 8; ++nt) {
            mx0 = fmaxf(mx0, fmaxf(s[nt][0], s[nt][1]));
            mx1 = fmaxf(mx1, fmaxf(s[nt][2], s[nt][3]));
        }
        mx0 = fmaxf(mx0, __shfl_xor_sync(0xffffffffu, mx0, 1));
        mx0 = fmaxf(mx0, __shfl_xor_sync(0xffffffffu, mx0, 2));
        mx1 = fmaxf(mx1, __shfl_xor_sync(0xffffffffu, mx1, 1));
        mx1 = fmaxf(mx1, __shfl_xor_sync(0xffffffffu, mx1, 2));

        float mn0 = fmaxf(m0, mx0), mn1 = fmaxf(m1, mx1);
        float al0 = fexp2(CE * (m0 - mn0)), al1 = fexp2(CE * (m1 - mn1));
        m0 = mn0; m1 = mn1;

        float sum0 = 0.f, sum1 = 0.f;
#pragma unroll
        for (int nt = 0; nt < 8; ++nt) {
            s[nt][0] = fexp2(CE * (s[nt][0] - m0));
            s[nt][1] = fexp2(CE * (s[nt][1] - m0));
            s[nt][2] = fexp2(CE * (s[nt][2] - m1));
            s[nt][3] = fexp2(CE * (s[nt][3] - m1));
            sum0 += s[nt][0] + s[nt][1];
            sum1 += s[nt][2] + s[nt][3];
        }
        sum0 += __shfl_xor_sync(0xffffffffu, sum0, 1);
        sum0 += __shfl_xor_sync(0xffffffffu, sum0, 2);
        sum1 += __shfl_xor_sync(0xffffffffu, sum1, 1);
        sum1 += __shfl_xor_sync(0xffffffffu, sum1, 2);
        l0 = l0 * al0 + sum0;
        l1 = l1 * al1 + sum1;
#pragma unroll
        for (int dt = 0; dt < 8; ++dt) {
            o[dt][0] *= al0; o[dt][1] *= al0; o[dt][2] *= al1; o[dt][3] *= al1;
        }

        // ---- PV: O += P V ----
#pragma unroll
        for (int kt = 0; kt < 8; ++kt) {
            uint32_t pa[4];
            cfrag_to_afrag(s[kt], pa);
#pragma unroll
            for (int dt = 0; dt < 8; ++dt) {
                uint32_t bf[2];
                const float* base = Vc + (kt * 8 + q4) * 72 + dt * 8 + g;
                bf[0] = __float_as_uint(base[0]);
                bf[1] = __float_as_uint(base[4 * 72]);
                mma8(o[dt], pa, bf);
            }
        }
        __syncthreads();
    }

    // ---- epilogue: normalize + tf32-round into [m][h*64+d] for proj ----
    const float inv0 = 1.0f / l0, inv1 = 1.0f / l1;
    const int b = bh >> 4, h = bh & 15;
    const int r0 = q0 + wq + g, r1 = r0 + 8;
    float* O0 = g_attn + ((size_t)(b * S_LEN) + r0) * H_DIM + h * HD;
    float* O1 = g_attn + ((size_t)(b * S_LEN) + r1) * H_DIM + h * HD;
#pragma unroll
    for (int dt = 0; dt < 8; ++dt) {
        int col = dt * 8 + q4 * 2;
        *(float2*)(O0 + col) = make_float2(f2tf32f(o[dt][0] * inv0), f2tf32f(o[dt][1] * inv0));
        *(float2*)(O1 + col) = make_float2(f2tf32f(o[dt][2] * inv1), f2tf32f(o[dt][3] * inv1));
    }
}

// ================= launch =================
extern "C" void kernel_launch(void* const* d_in, const int* in_sizes, int n_in,
                              void* d_out, int out_size)
{
    const float* x     = (const float*)d_in[0];   // [2,2048,1024]
    const float* Wqkv  = (const float*)d_in[1];   // [3072,1024]
    const float* Wproj = (const float*)d_in[2];   // [1024,1024]
    float* out = (float*)d_out;                   // [2,2048,1024]

    const int GEMM_SMEM  = 2 * 2 * 128 * 36 * 4;            // 73728
    const int FLASH_SMEM = (128 * 68 + 2 * 64 * 68 + 2 * 64 * 72) * 4; // 106496
    cudaFuncSetAttribute(gemm_qkv,  cudaFuncAttributeMaxDynamicSharedMemorySize, GEMM_SMEM);
    cudaFuncSetAttribute(gemm_proj, cudaFuncAttributeMaxDynamicSharedMemorySize, GEMM_SMEM);
    cudaFuncSetAttribute(flash_attn, cudaFuncAttributeMaxDynamicSharedMemorySize, FLASH_SMEM);

    init_rope_tables<<<(S_LEN * 32 + 255) / 256, 256>>>();
    cvt_x<<<(M_ROWS * H_DIM / 4 + 255) / 256, 256>>>(x);
    cvt_wqkv<<<(QKV_N * H_DIM / 4 + 255) / 256, 256>>>(Wqkv);
    cvt_wproj<<<(H_DIM * H_DIM / 4 + 255) / 256, 256>>>(Wproj);

    gemm_qkv<<<dim3(QKV_N / 128, M_ROWS / 128), 256, GEMM_SMEM>>>(nullptr);
    rope_permute<<<(3 << 22) / 256, 256>>>();
    flash_attn<<<dim3(S_LEN / 128, BH_TOT), 256, FLASH_SMEM>>>();
    gemm_proj<<<dim3(H_DIM / 128, M_ROWS / 128), 256, GEMM_SMEM>>>(out);
}